// round 7
// baseline (speedup 1.0000x reference)
#include <cuda_runtime.h>
#include <cuda_fp16.h>
#include <cstdint>
#include <cstddef>

// Problem sizes
static constexpr int M = 8192;   // tokens
static constexpr int K = 4096;   // in features
static constexpr int N = 4096;   // out features

// GEMM tiling: CTA 256x128x64, 8 warps (4 M x 2 N), warp tile 64x64, 256 threads.
// f16-accumulate MMA probe: fragments accumulate 4 MMAs in fp16, promoted to fp32 each k-iter.
static constexpr int BM = 256;
static constexpr int BN = 128;
static constexpr int BK = 64;                    // 64 fp16 = 128 B per row
static constexpr int NIT = K / BK;               // 64
static constexpr int STAGES = 4;
static constexpr int A_STAGE_BYTES = BM * 128;   // 32 KB
static constexpr int B_STAGE_BYTES = BN * 128;   // 16 KB
static constexpr int STAGE_BYTES = A_STAGE_BYTES + B_STAGE_BYTES;  // 48 KB
static constexpr int DYN_SMEM = 1024 + STAGES * STAGE_BYTES;       // ~193 KB

// Scratch (static device arrays are allowed; cudaMalloc is not)
__device__ __half g_A[(size_t)M * K];   // sign(x) as fp16, [M,K] row-major
__device__ __half g_B[(size_t)N * K];   // W^T as fp16,     [N,K] row-major (= col-major B)

// ---------------- PTX helpers (baseline sm_103, no 'a' features) ----------------
__device__ __forceinline__ uint32_t smem_u32(const void* p) {
    uint32_t a;
    asm("{ .reg .u64 t; cvta.to.shared.u64 t, %1; cvt.u32.u64 %0, t; }" : "=r"(a) : "l"(p));
    return a;
}
__device__ __forceinline__ void cp_async16(uint32_t s, const void* g) {
    asm volatile("cp.async.cg.shared.global [%0], [%1], 16;" :: "r"(s), "l"(g));
}
__device__ __forceinline__ void cp_commit() {
    asm volatile("cp.async.commit_group;" ::: "memory");
}
template <int NWAIT>
__device__ __forceinline__ void cp_wait() {
    asm volatile("cp.async.wait_group %0;" :: "n"(NWAIT) : "memory");
}
__device__ __forceinline__ void ldsm_x4(uint32_t& r0, uint32_t& r1, uint32_t& r2, uint32_t& r3,
                                        uint32_t addr) {
    asm volatile("ldmatrix.sync.aligned.m8n8.x4.shared.b16 {%0,%1,%2,%3}, [%4];"
                 : "=r"(r0), "=r"(r1), "=r"(r2), "=r"(r3) : "r"(addr));
}
// f16-accumulate MMA: D(f16x2 pair) = A*B + D
__device__ __forceinline__ void mma16816_h(uint32_t& d0, uint32_t& d1,
                                           uint32_t a0, uint32_t a1, uint32_t a2, uint32_t a3,
                                           uint32_t b0, uint32_t b1) {
    asm volatile(
        "mma.sync.aligned.m16n8k16.row.col.f16.f16.f16.f16 "
        "{%0,%1}, {%2,%3,%4,%5}, {%6,%7}, {%0,%1};"
        : "+r"(d0), "+r"(d1)
        : "r"(a0), "r"(a1), "r"(a2), "r"(a3), "r"(b0), "r"(b1));
}
// SW128-style swizzle: XOR 16B-chunk index with (row & 7)
__device__ __forceinline__ uint32_t swz(uint32_t off) { return off ^ ((off >> 3) & 0x70); }

// ---------------- Kernel 1: binarize x -> fp16 {+1,-1} ----------------
__global__ void binarize_kernel(const float4* __restrict__ x4, int n4) {
    int i = blockIdx.x * blockDim.x + threadIdx.x;
    const int stride = gridDim.x * blockDim.x;
    const __half one = __float2half_rn(1.0f);
    const __half neg = __float2half_rn(-1.0f);
    uint2* a8 = reinterpret_cast<uint2*>(g_A);
    for (; i < n4; i += stride) {
        float4 v = x4[i];
        __half2 h0 = __halves2half2(v.x > 0.0f ? one : neg, v.y > 0.0f ? one : neg);
        __half2 h1 = __halves2half2(v.z > 0.0f ? one : neg, v.w > 0.0f ? one : neg);
        uint2 pk;
        pk.x = *reinterpret_cast<uint32_t*>(&h0);
        pk.y = *reinterpret_cast<uint32_t*>(&h1);
        a8[i] = pk;
    }
}

// ---------------- Kernel 2: W [K,N] fp32 -> g_B [N,K] fp16 (transpose+convert) ----------------
__global__ void wconv_kernel(const float* __restrict__ W) {
    __shared__ float t[32][33];
    const int n0 = blockIdx.x * 32;
    const int k0 = blockIdx.y * 32;
    const int tx = threadIdx.x, ty = threadIdx.y;   // 32 x 8
#pragma unroll
    for (int r = 0; r < 4; ++r)
        t[ty + 8 * r][tx] = W[(size_t)(k0 + ty + 8 * r) * N + n0 + tx];
    __syncthreads();
#pragma unroll
    for (int r = 0; r < 4; ++r)
        g_B[(size_t)(n0 + ty + 8 * r) * K + k0 + tx] = __float2half_rn(t[tx][ty + 8 * r]);
}

// ---------------- Kernel 3: mma.sync f16-acc GEMM + bias ----------------
__device__ __forceinline__ void load_stage(uint32_t tile0, int m0, int n0, int k_it, int slot,
                                           int tid) {
    const int k0 = k_it * BK;
    const uint32_t sa = tile0 + slot * STAGE_BYTES;
    const uint32_t sbm = sa + A_STAGE_BYTES;
    // A: 2048 chunks, B: 1024 chunks; 3072 / 256 threads = 12 each
#pragma unroll
    for (int c = tid; c < 3072; c += 256) {
        if (c < 2048) {
            const int r = c >> 3, j = c & 7;
            cp_async16(sa + swz((uint32_t)(r * 128 + j * 16)),
                       g_A + (((size_t)(m0 + r)) << 12) + k0 + (j << 3));
        } else {
            const int c2 = c - 2048;
            const int r = c2 >> 3, j = c2 & 7;
            cp_async16(sbm + swz((uint32_t)(r * 128 + j * 16)),
                       g_B + (((size_t)(n0 + r)) << 12) + k0 + (j << 3));
        }
    }
}

__global__ void __launch_bounds__(256, 1) gemm_kernel(float* __restrict__ out,
                                                      const float* __restrict__ bias) {
    extern __shared__ char smem[];
    const uint32_t tile0 = (smem_u32(smem) + 1023) & ~1023u;
    const int tid = threadIdx.x;
    const int wid = tid >> 5;
    const int lane = tid & 31;
    const int m0 = blockIdx.y * BM;
    const int n0 = blockIdx.x * BN;
    const int warp_m = wid & 3;        // 0..3 -> 64 rows each
    const int warp_n = wid >> 2;       // 0..1 -> 64 cols each

    // Swizzled ldmatrix offsets (kk=0).
    // A row-major m16k16 x4
    uint32_t aoff[4];
#pragma unroll
    for (int mi = 0; mi < 4; ++mi) {
        const int row = warp_m * 64 + mi * 16 + (lane & 15);
        aoff[mi] = swz((uint32_t)(row * 128) + (uint32_t)((lane >> 4) << 4));
    }
    // B col-major n16k16 x4 (each covers 2 nj of n8)
    uint32_t boff[4];
#pragma unroll
    for (int pj = 0; pj < 4; ++pj) {
        const int row = warp_n * 64 + pj * 16 + (lane & 7) + ((lane >> 4) << 3);
        boff[pj] = swz((uint32_t)(row * 128) + (uint32_t)(((lane >> 3) & 1) << 4));
    }

    float accf[4][8][4];       // fp32 master accumulators
    uint32_t acch[4][8][2];    // fp16 window accumulators (f16x2 pairs)
#pragma unroll
    for (int mi = 0; mi < 4; ++mi)
#pragma unroll
        for (int nj = 0; nj < 8; ++nj) {
#pragma unroll
            for (int c = 0; c < 4; ++c) accf[mi][nj][c] = 0.0f;
            acch[mi][nj][0] = 0u;
            acch[mi][nj][1] = 0u;
        }

    // Prologue: fill stages 0..2
#pragma unroll
    for (int p = 0; p < STAGES - 1; ++p) {
        load_stage(tile0, m0, n0, p, p, tid);
        cp_commit();
    }

    for (int it = 0; it < NIT; ++it) {
        cp_wait<STAGES - 2>();
        __syncthreads();

        if (it + STAGES - 1 < NIT)
            load_stage(tile0, m0, n0, it + STAGES - 1, (it + STAGES - 1) % STAGES, tid);
        cp_commit();

        const uint32_t sa = tile0 + (it % STAGES) * STAGE_BYTES;
        const uint32_t sbm = sa + A_STAGE_BYTES;

#pragma unroll
        for (int kk = 0; kk < 4; ++kk) {
            const uint32_t kx = (uint32_t)(kk << 5);
            uint32_t a[4][4];
#pragma unroll
            for (int mi = 0; mi < 4; ++mi)
                ldsm_x4(a[mi][0], a[mi][1], a[mi][2], a[mi][3], sa + (aoff[mi] ^ kx));
            uint32_t b[8][2];
#pragma unroll
            for (int pj = 0; pj < 4; ++pj) {
                uint32_t r0, r1, r2, r3;
                ldsm_x4(r0, r1, r2, r3, sbm + (boff[pj] ^ kx));
                b[pj * 2 + 0][0] = r0; b[pj * 2 + 0][1] = r1;
                b[pj * 2 + 1][0] = r2; b[pj * 2 + 1][1] = r3;
            }
#pragma unroll
            for (int mi = 0; mi < 4; ++mi)
#pragma unroll
                for (int nj = 0; nj < 8; ++nj)
                    mma16816_h(acch[mi][nj][0], acch[mi][nj][1],
                               a[mi][0], a[mi][1], a[mi][2], a[mi][3],
                               b[nj][0], b[nj][1]);
        }

        // Promote this iter's fp16 window into the fp32 master, reset window.
#pragma unroll
        for (int mi = 0; mi < 4; ++mi)
#pragma unroll
            for (int nj = 0; nj < 8; ++nj) {
                const __half2 h0 = *reinterpret_cast<const __half2*>(&acch[mi][nj][0]);
                const __half2 h1 = *reinterpret_cast<const __half2*>(&acch[mi][nj][1]);
                const float2 f0 = __half22float2(h0);
                const float2 f1 = __half22float2(h1);
                accf[mi][nj][0] += f0.x;
                accf[mi][nj][1] += f0.y;
                accf[mi][nj][2] += f1.x;
                accf[mi][nj][3] += f1.y;
                acch[mi][nj][0] = 0u;
                acch[mi][nj][1] = 0u;
            }
    }

    // Epilogue: c0,c1 -> (row=g, col=tg*2+{0,1}); c2,c3 -> row=g+8
    const int g = lane >> 2, tg = lane & 3;
#pragma unroll
    for (int mi = 0; mi < 4; ++mi) {
        const int r0 = m0 + warp_m * 64 + mi * 16 + g;
        float* o0 = out + (size_t)r0 * N;
        float* o1 = out + (size_t)(r0 + 8) * N;
#pragma unroll
        for (int nj = 0; nj < 8; ++nj) {
            const int col = n0 + warp_n * 64 + nj * 8 + tg * 2;
            const float b0 = __ldg(bias + col);
            const float b1 = __ldg(bias + col + 1);
            float2 v0 = make_float2(accf[mi][nj][0] + b0, accf[mi][nj][1] + b1);
            float2 v1 = make_float2(accf[mi][nj][2] + b0, accf[mi][nj][3] + b1);
            *reinterpret_cast<float2*>(o0 + col) = v0;
            *reinterpret_cast<float2*>(o1 + col) = v1;
        }
    }
}

// ---------------- launch ----------------
extern "C" void kernel_launch(void* const* d_in, const int* in_sizes, int n_in,
                              void* d_out, int out_size) {
    const float* x    = (const float*)d_in[0];
    const float* W    = (const float*)d_in[1];
    const float* bias = (const float*)d_in[2];
    float* out = (float*)d_out;

    binarize_kernel<<<4096, 256>>>((const float4*)x, (M * K) / 4);
    wconv_kernel<<<dim3(N / 32, K / 32), dim3(32, 8)>>>(W);

    cudaFuncSetAttribute(gemm_kernel, cudaFuncAttributeMaxDynamicSharedMemorySize, DYN_SMEM);
    gemm_kernel<<<dim3(N / BN, M / BM), 256, DYN_SMEM>>>(out, bias);
}

// round 9
// speedup vs baseline: 1.1030x; 1.1030x over previous
#include <cuda_runtime.h>
#include <cuda_fp16.h>
#include <cstdint>
#include <cstddef>

// Problem sizes
static constexpr int M = 8192;   // tokens
static constexpr int K = 4096;   // in features
static constexpr int N = 4096;   // out features

// GEMM tiling: CTA 256x128x64, 16 warps (4 M x 4 N), warp tile 64x32, 512 threads.
static constexpr int BM = 256;
static constexpr int BN = 128;
static constexpr int BK = 64;                    // 64 fp16 = 128 B per row
static constexpr int NIT = K / BK;               // 64
static constexpr int STAGES = 4;
static constexpr int A_STAGE_BYTES = BM * 128;   // 32 KB
static constexpr int B_STAGE_BYTES = BN * 128;   // 16 KB
static constexpr int STAGE_BYTES = A_STAGE_BYTES + B_STAGE_BYTES;  // 48 KB
static constexpr int DYN_SMEM = 1024 + STAGES * STAGE_BYTES;       // ~193 KB

// Scratch (static device arrays are allowed; cudaMalloc is not)
// A as BITS: 1 bit per element, tiled [tm(32)][tk(64)] tiles of 256rows x 64k.
// Within a tile: word index = half*256 + row, where half selects k-bits [0,32) or [32,64).
__device__ uint32_t g_Abits[(size_t)M * K / 32];   // 4 MB
__device__ __half   g_B[(size_t)N * K];            // W^T fp16, [N,K] row-major

// ---------------- PTX helpers (baseline sm_103, no 'a' features) ----------------
__device__ __forceinline__ uint32_t smem_u32(const void* p) {
    uint32_t a;
    asm("{ .reg .u64 t; cvta.to.shared.u64 t, %1; cvt.u32.u64 %0, t; }" : "=r"(a) : "l"(p));
    return a;
}
__device__ __forceinline__ void cp_async16(uint32_t s, const void* g) {
    asm volatile("cp.async.cg.shared.global [%0], [%1], 16;" :: "r"(s), "l"(g));
}
__device__ __forceinline__ void cp_commit() {
    asm volatile("cp.async.commit_group;" ::: "memory");
}
template <int NWAIT>
__device__ __forceinline__ void cp_wait() {
    asm volatile("cp.async.wait_group %0;" :: "n"(NWAIT) : "memory");
}
__device__ __forceinline__ void ldsm_x4(uint32_t& r0, uint32_t& r1, uint32_t& r2, uint32_t& r3,
                                        uint32_t addr) {
    asm volatile("ldmatrix.sync.aligned.m8n8.x4.shared.b16 {%0,%1,%2,%3}, [%4];"
                 : "=r"(r0), "=r"(r1), "=r"(r2), "=r"(r3) : "r"(addr));
}
__device__ __forceinline__ void mma16816(float& d0, float& d1, float& d2, float& d3,
                                         uint32_t a0, uint32_t a1, uint32_t a2, uint32_t a3,
                                         uint32_t b0, uint32_t b1) {
    asm volatile(
        "mma.sync.aligned.m16n8k16.row.col.f32.f16.f16.f32 "
        "{%0,%1,%2,%3}, {%4,%5,%6,%7}, {%8,%9}, {%0,%1,%2,%3};"
        : "+f"(d0), "+f"(d1), "+f"(d2), "+f"(d3)
        : "r"(a0), "r"(a1), "r"(a2), "r"(a3), "r"(b0), "r"(b1));
}
// SW128-style swizzle: XOR 16B-chunk index with (row & 7)
__device__ __forceinline__ uint32_t swz(uint32_t off) { return off ^ ((off >> 3) & 0x70); }

// ---------------- Kernel 1: binarize x -> bit array ----------------
// One thread builds one uint32 = 32 k-bits of one row (bit=1 <=> x>0 <=> +1).
__global__ void binbits_kernel(const float4* __restrict__ x4) {
    const int gid = blockIdx.x * 256 + threadIdx.x;      // 0 .. M*K/32-1
    const int tile = gid >> 9;                            // 512 words per tile
    const int w = gid & 511;
    const int half = w >> 8;                              // k-half within 64-k tile
    const int row = w & 255;
    const int m = ((tile >> 6) << 8) | row;
    const int k = ((tile & 63) << 6) | (half << 5);
    const float4* p = x4 + (((size_t)m * K + k) >> 2);
    uint32_t bits = 0;
#pragma unroll
    for (int j = 0; j < 8; ++j) {
        const float4 v = p[j];
        bits |= (v.x > 0.0f ? 1u : 0u) << (4 * j + 0);
        bits |= (v.y > 0.0f ? 1u : 0u) << (4 * j + 1);
        bits |= (v.z > 0.0f ? 1u : 0u) << (4 * j + 2);
        bits |= (v.w > 0.0f ? 1u : 0u) << (4 * j + 3);
    }
    g_Abits[gid] = bits;
}

// ---------------- Kernel 2: W [K,N] fp32 -> g_B [N,K] fp16 (transpose+convert) ----------------
// Tile 32 n x 64 k; half2 stores. 256 threads: load 8 k-rows each, store 4 (n, k-pair) each.
__global__ void wconv_kernel(const float* __restrict__ W) {
    __shared__ float t[64][33];
    const int n0 = blockIdx.x * 32;
    const int k0 = blockIdx.y * 64;
    const int tx = threadIdx.x, ty = threadIdx.y;   // 32 x 8
#pragma unroll
    for (int r = 0; r < 8; ++r)
        t[ty + 8 * r][tx] = W[(size_t)(k0 + ty + 8 * r) * N + n0 + tx];
    __syncthreads();
#pragma unroll
    for (int r = 0; r < 4; ++r) {
        const int n = ty + 8 * r;                   // 0..31 (n within tile)
        const __half2 h = __floats2half2_rn(t[2 * tx][n], t[2 * tx + 1][n]);
        *reinterpret_cast<__half2*>(g_B + (size_t)(n0 + n) * K + k0 + 2 * tx) = h;
    }
}

// ---------------- Kernel 3: mma.sync fp16 GEMM + bias ----------------
// A from bit array (expand in regs -> STS), B via cp.async.
// Thread -> A word: row = tid & 255, half = tid >> 8 (matches binbits tile layout).
__device__ __forceinline__ void store_A_bits(uint32_t sa_slot, uint32_t bits, int tid) {
    const int row = tid & 255;
    const int half = tid >> 8;
    const uint32_t base = (uint32_t)(row * 128 + half * 64);
#pragma unroll
    for (int q = 0; q < 4; ++q) {
        const uint32_t b = bits >> (q * 8);
        const uint32_t v0 = 0xBC00BC00u ^ ((b & 1u) << 15) ^ ((b & 2u) << 30);
        const uint32_t v1 = 0xBC00BC00u ^ (((b >> 2) & 1u) << 15) ^ (((b >> 3) & 1u) << 31);
        const uint32_t v2 = 0xBC00BC00u ^ (((b >> 4) & 1u) << 15) ^ (((b >> 5) & 1u) << 31);
        const uint32_t v3 = 0xBC00BC00u ^ (((b >> 6) & 1u) << 15) ^ (((b >> 7) & 1u) << 31);
        const uint32_t addr = sa_slot + swz(base + q * 16);
        asm volatile("st.shared.v4.b32 [%0], {%1,%2,%3,%4};"
                     :: "r"(addr), "r"(v0), "r"(v1), "r"(v2), "r"(v3));
    }
}
__device__ __forceinline__ void load_B(uint32_t sb_slot, int n0, int k_it, int tid) {
    const int k0 = k_it * BK;
    // 128 rows x 8 chunks = 1024 / 512 threads = 2 each
#pragma unroll
    for (int c = tid; c < 1024; c += 512) {
        const int r = c >> 3, j = c & 7;
        cp_async16(sb_slot + swz((uint32_t)(r * 128 + j * 16)),
                   g_B + (((size_t)(n0 + r)) << 12) + k0 + (j << 3));
    }
}

__global__ void __launch_bounds__(512, 1) gemm_kernel(float* __restrict__ out,
                                                      const float* __restrict__ bias) {
    extern __shared__ char smem[];
    const uint32_t tile0 = (smem_u32(smem) + 1023) & ~1023u;
    const int tid = threadIdx.x;
    const int wid = tid >> 5;
    const int lane = tid & 31;
    const int m0 = blockIdx.y * BM;
    const int n0 = blockIdx.x * BN;
    const int warp_m = wid & 3;        // 0..3 -> 64 rows each
    const int warp_n = wid >> 2;       // 0..3 -> 32 cols each
    const size_t abit_base = ((size_t)blockIdx.y * 64) * 512 + tid;   // + stage*512

    // Swizzled ldmatrix offsets (kk=0).
    uint32_t aoff[4];
#pragma unroll
    for (int mi = 0; mi < 4; ++mi) {
        const int row = warp_m * 64 + mi * 16 + (lane & 15);
        aoff[mi] = swz((uint32_t)(row * 128) + (uint32_t)((lane >> 4) << 4));
    }
    uint32_t boff[2];
#pragma unroll
    for (int pj = 0; pj < 2; ++pj) {
        const int row = warp_n * 32 + pj * 16 + (lane & 7) + ((lane >> 4) << 3);
        boff[pj] = swz((uint32_t)(row * 128) + (uint32_t)(((lane >> 3) & 1) << 4));
    }

    float acc[4][4][4];   // [mi][nj][c]
#pragma unroll
    for (int mi = 0; mi < 4; ++mi)
#pragma unroll
        for (int nj = 0; nj < 4; ++nj)
#pragma unroll
            for (int c = 0; c < 4; ++c) acc[mi][nj][c] = 0.0f;

    // Prologue: fill stages 0..2
#pragma unroll
    for (int p = 0; p < STAGES - 1; ++p) {
        const uint32_t slot = tile0 + p * STAGE_BYTES;
        const uint32_t bits = __ldg(&g_Abits[abit_base + (size_t)p * 512]);
        store_A_bits(slot, bits, tid);
        load_B(slot + A_STAGE_BYTES, n0, p, tid);
        cp_commit();
    }
    uint32_t bits_pend = __ldg(&g_Abits[abit_base + (size_t)(STAGES - 1) * 512]);

    for (int it = 0; it < NIT; ++it) {
        cp_wait<STAGES - 2>();
        __syncthreads();

        // Fill stage it+3 into the slot freed by the barrier (A from prefetched bits).
        if (it + STAGES - 1 < NIT) {
            const uint32_t slot = tile0 + ((it + STAGES - 1) % STAGES) * STAGE_BYTES;
            store_A_bits(slot, bits_pend, tid);
            load_B(slot + A_STAGE_BYTES, n0, it + STAGES - 1, tid);
        }
        cp_commit();
        // Prefetch bits for stage it+4 (consumed next iter; full iter of latency cover).
        if (it + STAGES < NIT)
            bits_pend = g_Abits[abit_base + (size_t)(it + STAGES) * 512];

        const uint32_t sa = tile0 + (it % STAGES) * STAGE_BYTES;
        const uint32_t sbm = sa + A_STAGE_BYTES;

        // Software-pipelined fragment flow (R6 core):
        uint32_t bcur[4][2], bnxt[4][2];
        {
            uint32_t r0, r1, r2, r3;
            ldsm_x4(r0, r1, r2, r3, sbm + boff[0]);
            bcur[0][0] = r0; bcur[0][1] = r1; bcur[1][0] = r2; bcur[1][1] = r3;
            ldsm_x4(r0, r1, r2, r3, sbm + boff[1]);
            bcur[2][0] = r0; bcur[2][1] = r1; bcur[3][0] = r2; bcur[3][1] = r3;
        }
        uint32_t acur[4], anxt[4];
        ldsm_x4(acur[0], acur[1], acur[2], acur[3], sa + aoff[0]);

#pragma unroll
        for (int kk = 0; kk < 4; ++kk) {
            const uint32_t kx = (uint32_t)(kk << 5);
            const uint32_t kxn = (uint32_t)((kk + 1) << 5);
            if (kk < 3) {   // prefetch next kk's B
                uint32_t r0, r1, r2, r3;
                ldsm_x4(r0, r1, r2, r3, sbm + (boff[0] ^ kxn));
                bnxt[0][0] = r0; bnxt[0][1] = r1; bnxt[1][0] = r2; bnxt[1][1] = r3;
                ldsm_x4(r0, r1, r2, r3, sbm + (boff[1] ^ kxn));
                bnxt[2][0] = r0; bnxt[2][1] = r1; bnxt[3][0] = r2; bnxt[3][1] = r3;
            }
#pragma unroll
            for (int mi = 0; mi < 4; ++mi) {
                if (mi < 3)
                    ldsm_x4(anxt[0], anxt[1], anxt[2], anxt[3], sa + (aoff[mi + 1] ^ kx));
                else if (kk < 3)
                    ldsm_x4(anxt[0], anxt[1], anxt[2], anxt[3], sa + (aoff[0] ^ kxn));
#pragma unroll
                for (int nj = 0; nj < 4; ++nj)
                    mma16816(acc[mi][nj][0], acc[mi][nj][1], acc[mi][nj][2], acc[mi][nj][3],
                             acur[0], acur[1], acur[2], acur[3],
                             bcur[nj][0], bcur[nj][1]);
#pragma unroll
                for (int q = 0; q < 4; ++q) acur[q] = anxt[q];
            }
            if (kk < 3) {
#pragma unroll
                for (int nj = 0; nj < 4; ++nj) {
                    bcur[nj][0] = bnxt[nj][0];
                    bcur[nj][1] = bnxt[nj][1];
                }
            }
        }
    }

    // Epilogue
    const int g = lane >> 2, tg = lane & 3;
#pragma unroll
    for (int mi = 0; mi < 4; ++mi) {
        const int r0 = m0 + warp_m * 64 + mi * 16 + g;
        float* o0 = out + (size_t)r0 * N;
        float* o1 = out + (size_t)(r0 + 8) * N;
#pragma unroll
        for (int nj = 0; nj < 4; ++nj) {
            const int col = n0 + warp_n * 32 + nj * 8 + tg * 2;
            const float b0 = __ldg(bias + col);
            const float b1 = __ldg(bias + col + 1);
            float2 v0 = make_float2(acc[mi][nj][0] + b0, acc[mi][nj][1] + b1);
            float2 v1 = make_float2(acc[mi][nj][2] + b0, acc[mi][nj][3] + b1);
            *reinterpret_cast<float2*>(o0 + col) = v0;
            *reinterpret_cast<float2*>(o1 + col) = v1;
        }
    }
}

// ---------------- launch ----------------
extern "C" void kernel_launch(void* const* d_in, const int* in_sizes, int n_in,
                              void* d_out, int out_size) {
    const float* x    = (const float*)d_in[0];
    const float* W    = (const float*)d_in[1];
    const float* bias = (const float*)d_in[2];
    float* out = (float*)d_out;

    binbits_kernel<<<(M * K / 32) / 256, 256>>>((const float4*)x);
    wconv_kernel<<<dim3(N / 32, K / 64), dim3(32, 8)>>>(W);

    cudaFuncSetAttribute(gemm_kernel, cudaFuncAttributeMaxDynamicSharedMemorySize, DYN_SMEM);
    gemm_kernel<<<dim3(N / BN, M / BM), 512, DYN_SMEM>>>(out, bias);
}

// round 10
// speedup vs baseline: 1.2426x; 1.1266x over previous
#include <cuda_runtime.h>
#include <cuda_fp16.h>
#include <cstdint>
#include <cstddef>

// Problem sizes
static constexpr int M = 8192;   // tokens
static constexpr int K = 4096;   // in features
static constexpr int N = 4096;   // out features

// GEMM tiling: CTA 256x128x64, 16 warps (4 M x 4 N), warp tile 64x32, 512 threads.
static constexpr int BM = 256;
static constexpr int BN = 128;
static constexpr int BK = 64;                    // 64 fp16 = 128 B per row
static constexpr int NIT = K / BK;               // 64
static constexpr int STAGES = 4;
static constexpr int A_STAGE_BYTES = BM * 128;   // 32 KB
static constexpr int B_STAGE_BYTES = BN * 128;   // 16 KB
static constexpr int STAGE_BYTES = A_STAGE_BYTES + B_STAGE_BYTES;  // 48 KB
static constexpr int DYN_SMEM = 1024 + STAGES * STAGE_BYTES;       // ~193 KB

// Scratch (static device arrays are allowed; cudaMalloc is not)
__device__ __half g_A[(size_t)M * K];   // sign(x) as fp16, [M,K] row-major
__device__ __half g_B[(size_t)N * K];   // W^T as fp16,     [N,K] row-major

// ---------------- PTX helpers (baseline sm_103, no 'a' features) ----------------
__device__ __forceinline__ uint32_t smem_u32(const void* p) {
    uint32_t a;
    asm("{ .reg .u64 t; cvta.to.shared.u64 t, %1; cvt.u32.u64 %0, t; }" : "=r"(a) : "l"(p));
    return a;
}
__device__ __forceinline__ void cp_async16(uint32_t s, const void* g) {
    asm volatile("cp.async.cg.shared.global [%0], [%1], 16;" :: "r"(s), "l"(g));
}
__device__ __forceinline__ void cp_commit() {
    asm volatile("cp.async.commit_group;" ::: "memory");
}
template <int NWAIT>
__device__ __forceinline__ void cp_wait() {
    asm volatile("cp.async.wait_group %0;" :: "n"(NWAIT) : "memory");
}
__device__ __forceinline__ void ldsm_x4(uint32_t& r0, uint32_t& r1, uint32_t& r2, uint32_t& r3,
                                        uint32_t addr) {
    asm volatile("ldmatrix.sync.aligned.m8n8.x4.shared.b16 {%0,%1,%2,%3}, [%4];"
                 : "=r"(r0), "=r"(r1), "=r"(r2), "=r"(r3) : "r"(addr));
}
__device__ __forceinline__ void mma16816(float& d0, float& d1, float& d2, float& d3,
                                         uint32_t a0, uint32_t a1, uint32_t a2, uint32_t a3,
                                         uint32_t b0, uint32_t b1) {
    asm volatile(
        "mma.sync.aligned.m16n8k16.row.col.f32.f16.f16.f32 "
        "{%0,%1,%2,%3}, {%4,%5,%6,%7}, {%8,%9}, {%0,%1,%2,%3};"
        : "+f"(d0), "+f"(d1), "+f"(d2), "+f"(d3)
        : "r"(a0), "r"(a1), "r"(a2), "r"(a3), "r"(b0), "r"(b1));
}
// SW128-style swizzle: XOR 16B-chunk index with (row & 7)
__device__ __forceinline__ uint32_t swz(uint32_t off) { return off ^ ((off >> 3) & 0x70); }

// ---------------- Kernel 1: fused prep ----------------
// blocks [0, 4096): binarize x -> g_A (fp16 {+1,-1})
// blocks [4096, 4096+8192): W [K,N] fp32 -> g_B [N,K] fp16 (transpose+convert, 32n x 64k tiles)
static constexpr int BIN_BLOCKS = 4096;
static constexpr int WCONV_BLOCKS = (N / 32) * (K / 64);   // 8192
__global__ void prep_kernel(const float4* __restrict__ x4, const float* __restrict__ W) {
    if (blockIdx.x < BIN_BLOCKS) {
        const int n4 = (M * K) / 4;
        int i = blockIdx.x * 256 + threadIdx.x;
        const int stride = BIN_BLOCKS * 256;
        const __half one = __float2half_rn(1.0f);
        const __half neg = __float2half_rn(-1.0f);
        uint2* a8 = reinterpret_cast<uint2*>(g_A);
        for (; i < n4; i += stride) {
            float4 v = x4[i];
            __half2 h0 = __halves2half2(v.x > 0.0f ? one : neg, v.y > 0.0f ? one : neg);
            __half2 h1 = __halves2half2(v.z > 0.0f ? one : neg, v.w > 0.0f ? one : neg);
            uint2 pk;
            pk.x = *reinterpret_cast<uint32_t*>(&h0);
            pk.y = *reinterpret_cast<uint32_t*>(&h1);
            a8[i] = pk;
        }
    } else {
        __shared__ float t[64][33];
        const int bid = blockIdx.x - BIN_BLOCKS;
        const int n0 = (bid & 127) * 32;       // N/32 = 128
        const int k0 = (bid >> 7) * 64;
        const int tx = threadIdx.x & 31, ty = threadIdx.x >> 5;   // 32 x 8
#pragma unroll
        for (int r = 0; r < 8; ++r)
            t[ty + 8 * r][tx] = W[(size_t)(k0 + ty + 8 * r) * N + n0 + tx];
        __syncthreads();
#pragma unroll
        for (int r = 0; r < 4; ++r) {
            const int n = ty + 8 * r;          // 0..31
            const __half2 h = __floats2half2_rn(t[2 * tx][n], t[2 * tx + 1][n]);
            *reinterpret_cast<__half2*>(g_B + (size_t)(n0 + n) * K + k0 + 2 * tx) = h;
        }
    }
}

// ---------------- Kernel 2: mma.sync fp16 GEMM + bias (R6 core, best measured) ----------------
__device__ __forceinline__ void load_stage(uint32_t tile0, int m0, int n0, int k_it, int slot,
                                           int tid) {
    const int k0 = k_it * BK;
    const uint32_t sa = tile0 + slot * STAGE_BYTES;
    const uint32_t sbm = sa + A_STAGE_BYTES;
#pragma unroll
    for (int c = tid; c < 3072; c += 512) {
        if (c < 2048) {
            const int r = c >> 3, j = c & 7;
            cp_async16(sa + swz((uint32_t)(r * 128 + j * 16)),
                       g_A + (((size_t)(m0 + r)) << 12) + k0 + (j << 3));
        } else {
            const int c2 = c - 2048;
            const int r = c2 >> 3, j = c2 & 7;
            cp_async16(sbm + swz((uint32_t)(r * 128 + j * 16)),
                       g_B + (((size_t)(n0 + r)) << 12) + k0 + (j << 3));
        }
    }
}

__global__ void __launch_bounds__(512, 1) gemm_kernel(float* __restrict__ out,
                                                      const float* __restrict__ bias) {
    extern __shared__ char smem[];
    const uint32_t tile0 = (smem_u32(smem) + 1023) & ~1023u;
    const int tid = threadIdx.x;
    const int wid = tid >> 5;
    const int lane = tid & 31;
    const int m0 = blockIdx.y * BM;
    const int n0 = blockIdx.x * BN;
    const int warp_m = wid & 3;        // 0..3 -> 64 rows each
    const int warp_n = wid >> 2;       // 0..3 -> 32 cols each

    // Swizzled ldmatrix offsets (kk=0).
    uint32_t aoff[4];
#pragma unroll
    for (int mi = 0; mi < 4; ++mi) {
        const int row = warp_m * 64 + mi * 16 + (lane & 15);
        aoff[mi] = swz((uint32_t)(row * 128) + (uint32_t)((lane >> 4) << 4));
    }
    uint32_t boff[2];
#pragma unroll
    for (int pj = 0; pj < 2; ++pj) {
        const int row = warp_n * 32 + pj * 16 + (lane & 7) + ((lane >> 4) << 3);
        boff[pj] = swz((uint32_t)(row * 128) + (uint32_t)(((lane >> 3) & 1) << 4));
    }

    float acc[4][4][4];   // [mi][nj][c]
#pragma unroll
    for (int mi = 0; mi < 4; ++mi)
#pragma unroll
        for (int nj = 0; nj < 4; ++nj)
#pragma unroll
            for (int c = 0; c < 4; ++c) acc[mi][nj][c] = 0.0f;

    // Prologue: fill stages 0..2
#pragma unroll
    for (int p = 0; p < STAGES - 1; ++p) {
        load_stage(tile0, m0, n0, p, p, tid);
        cp_commit();
    }

    for (int it = 0; it < NIT; ++it) {
        cp_wait<STAGES - 2>();
        __syncthreads();

        // Issue next stage's loads first so they overlap this iter's compute.
        if (it + STAGES - 1 < NIT)
            load_stage(tile0, m0, n0, it + STAGES - 1, (it + STAGES - 1) % STAGES, tid);
        cp_commit();

        const uint32_t sa = tile0 + (it % STAGES) * STAGE_BYTES;
        const uint32_t sbm = sa + A_STAGE_BYTES;

        // Software-pipelined fragment flow:
        //   B double-buffered across kk (16 regs), A rotated across mi (8 regs).
        uint32_t bcur[4][2], bnxt[4][2];
        {
            uint32_t r0, r1, r2, r3;
            ldsm_x4(r0, r1, r2, r3, sbm + boff[0]);
            bcur[0][0] = r0; bcur[0][1] = r1; bcur[1][0] = r2; bcur[1][1] = r3;
            ldsm_x4(r0, r1, r2, r3, sbm + boff[1]);
            bcur[2][0] = r0; bcur[2][1] = r1; bcur[3][0] = r2; bcur[3][1] = r3;
        }
        uint32_t acur[4], anxt[4];
        ldsm_x4(acur[0], acur[1], acur[2], acur[3], sa + aoff[0]);

#pragma unroll
        for (int kk = 0; kk < 4; ++kk) {
            const uint32_t kx = (uint32_t)(kk << 5);
            const uint32_t kxn = (uint32_t)((kk + 1) << 5);
            if (kk < 3) {   // prefetch next kk's B
                uint32_t r0, r1, r2, r3;
                ldsm_x4(r0, r1, r2, r3, sbm + (boff[0] ^ kxn));
                bnxt[0][0] = r0; bnxt[0][1] = r1; bnxt[1][0] = r2; bnxt[1][1] = r3;
                ldsm_x4(r0, r1, r2, r3, sbm + (boff[1] ^ kxn));
                bnxt[2][0] = r0; bnxt[2][1] = r1; bnxt[3][0] = r2; bnxt[3][1] = r3;
            }
#pragma unroll
            for (int mi = 0; mi < 4; ++mi) {
                if (mi < 3)
                    ldsm_x4(anxt[0], anxt[1], anxt[2], anxt[3], sa + (aoff[mi + 1] ^ kx));
                else if (kk < 3)
                    ldsm_x4(anxt[0], anxt[1], anxt[2], anxt[3], sa + (aoff[0] ^ kxn));
#pragma unroll
                for (int nj = 0; nj < 4; ++nj)
                    mma16816(acc[mi][nj][0], acc[mi][nj][1], acc[mi][nj][2], acc[mi][nj][3],
                             acur[0], acur[1], acur[2], acur[3],
                             bcur[nj][0], bcur[nj][1]);
#pragma unroll
                for (int q = 0; q < 4; ++q) acur[q] = anxt[q];
            }
            if (kk < 3) {
#pragma unroll
                for (int nj = 0; nj < 4; ++nj) {
                    bcur[nj][0] = bnxt[nj][0];
                    bcur[nj][1] = bnxt[nj][1];
                }
            }
        }
    }

    // Epilogue
    const int g = lane >> 2, tg = lane & 3;
#pragma unroll
    for (int mi = 0; mi < 4; ++mi) {
        const int r0 = m0 + warp_m * 64 + mi * 16 + g;
        float* o0 = out + (size_t)r0 * N;
        float* o1 = out + (size_t)(r0 + 8) * N;
#pragma unroll
        for (int nj = 0; nj < 4; ++nj) {
            const int col = n0 + warp_n * 32 + nj * 8 + tg * 2;
            const float b0 = __ldg(bias + col);
            const float b1 = __ldg(bias + col + 1);
            float2 v0 = make_float2(acc[mi][nj][0] + b0, acc[mi][nj][1] + b1);
            float2 v1 = make_float2(acc[mi][nj][2] + b0, acc[mi][nj][3] + b1);
            *reinterpret_cast<float2*>(o0 + col) = v0;
            *reinterpret_cast<float2*>(o1 + col) = v1;
        }
    }
}

// ---------------- launch ----------------
extern "C" void kernel_launch(void* const* d_in, const int* in_sizes, int n_in,
                              void* d_out, int out_size) {
    const float* x    = (const float*)d_in[0];
    const float* W    = (const float*)d_in[1];
    const float* bias = (const float*)d_in[2];
    float* out = (float*)d_out;

    prep_kernel<<<BIN_BLOCKS + WCONV_BLOCKS, 256>>>((const float4*)x, W);

    cudaFuncSetAttribute(gemm_kernel, cudaFuncAttributeMaxDynamicSharedMemorySize, DYN_SMEM);
    gemm_kernel<<<dim3(N / BN, M / BM), 512, DYN_SMEM>>>(out, bias);
}

// round 11
// speedup vs baseline: 1.2477x; 1.0041x over previous
#include <cuda_runtime.h>
#include <cuda_fp16.h>
#include <cstdint>
#include <cstddef>

// Problem sizes
static constexpr int M = 8192;   // tokens
static constexpr int K = 4096;   // in features
static constexpr int N = 4096;   // out features

// GEMM tiling: CTA 256x128x64, 16 warps (4 M x 4 N), warp tile 64x32, 512 threads.
static constexpr int BM = 256;
static constexpr int BN = 128;
static constexpr int BK = 64;                    // 64 fp16 = 128 B per row
static constexpr int NIT = K / BK;               // 64
static constexpr int STAGES = 4;
static constexpr int A_STAGE_BYTES = BM * 128;   // 32 KB
static constexpr int B_STAGE_BYTES = BN * 128;   // 16 KB
static constexpr int STAGE_BYTES = A_STAGE_BYTES + B_STAGE_BYTES;  // 48 KB
static constexpr int DYN_SMEM = 1024 + STAGES * STAGE_BYTES;       // ~193 KB

// Scratch (static device arrays are allowed; cudaMalloc is not)
__device__ __half g_A[(size_t)M * K];   // sign(x) as fp16, [M,K] row-major
__device__ __half g_B[(size_t)N * K];   // W^T as fp16,     [N,K] row-major

// ---------------- PTX helpers (baseline sm_103, no 'a' features) ----------------
__device__ __forceinline__ uint32_t smem_u32(const void* p) {
    uint32_t a;
    asm("{ .reg .u64 t; cvta.to.shared.u64 t, %1; cvt.u32.u64 %0, t; }" : "=r"(a) : "l"(p));
    return a;
}
__device__ __forceinline__ void cp_async16(uint32_t s, const void* g) {
    asm volatile("cp.async.cg.shared.global [%0], [%1], 16;" :: "r"(s), "l"(g));
}
__device__ __forceinline__ void cp_commit() {
    asm volatile("cp.async.commit_group;" ::: "memory");
}
template <int NWAIT>
__device__ __forceinline__ void cp_wait() {
    asm volatile("cp.async.wait_group %0;" :: "n"(NWAIT) : "memory");
}
__device__ __forceinline__ void ldsm_x4(uint32_t& r0, uint32_t& r1, uint32_t& r2, uint32_t& r3,
                                        uint32_t addr) {
    asm volatile("ldmatrix.sync.aligned.m8n8.x4.shared.b16 {%0,%1,%2,%3}, [%4];"
                 : "=r"(r0), "=r"(r1), "=r"(r2), "=r"(r3) : "r"(addr));
}
__device__ __forceinline__ void mma16816(float& d0, float& d1, float& d2, float& d3,
                                         uint32_t a0, uint32_t a1, uint32_t a2, uint32_t a3,
                                         uint32_t b0, uint32_t b1) {
    asm volatile(
        "mma.sync.aligned.m16n8k16.row.col.f32.f16.f16.f32 "
        "{%0,%1,%2,%3}, {%4,%5,%6,%7}, {%8,%9}, {%0,%1,%2,%3};"
        : "+f"(d0), "+f"(d1), "+f"(d2), "+f"(d3)
        : "r"(a0), "r"(a1), "r"(a2), "r"(a3), "r"(b0), "r"(b1));
}
// SW128-style swizzle: XOR 16B-chunk index with (row & 7)
__device__ __forceinline__ uint32_t swz(uint32_t off) { return off ^ ((off >> 3) & 0x70); }

// ---------------- Kernel 1: fused prep ----------------
static constexpr int BIN_BLOCKS = 4096;
static constexpr int WCONV_BLOCKS = (N / 32) * (K / 64);   // 8192
__global__ void prep_kernel(const float4* __restrict__ x4, const float* __restrict__ W) {
    if (blockIdx.x < BIN_BLOCKS) {
        const int n4 = (M * K) / 4;
        int i = blockIdx.x * 256 + threadIdx.x;
        const int stride = BIN_BLOCKS * 256;
        const __half one = __float2half_rn(1.0f);
        const __half neg = __float2half_rn(-1.0f);
        uint2* a8 = reinterpret_cast<uint2*>(g_A);
        for (; i < n4; i += stride) {
            float4 v = x4[i];
            __half2 h0 = __halves2half2(v.x > 0.0f ? one : neg, v.y > 0.0f ? one : neg);
            __half2 h1 = __halves2half2(v.z > 0.0f ? one : neg, v.w > 0.0f ? one : neg);
            uint2 pk;
            pk.x = *reinterpret_cast<uint32_t*>(&h0);
            pk.y = *reinterpret_cast<uint32_t*>(&h1);
            a8[i] = pk;
        }
    } else {
        __shared__ float t[64][33];
        const int bid = blockIdx.x - BIN_BLOCKS;
        const int n0 = (bid & 127) * 32;       // N/32 = 128
        const int k0 = (bid >> 7) * 64;
        const int tx = threadIdx.x & 31, ty = threadIdx.x >> 5;   // 32 x 8
#pragma unroll
        for (int r = 0; r < 8; ++r)
            t[ty + 8 * r][tx] = W[(size_t)(k0 + ty + 8 * r) * N + n0 + tx];
        __syncthreads();
#pragma unroll
        for (int r = 0; r < 4; ++r) {
            const int n = ty + 8 * r;          // 0..31
            const __half2 h = __floats2half2_rn(t[2 * tx][n], t[2 * tx + 1][n]);
            *reinterpret_cast<__half2*>(g_B + (size_t)(n0 + n) * K + k0 + 2 * tx) = h;
        }
    }
}

// ---------------- Kernel 2: mma.sync fp16 GEMM + bias ----------------
__device__ __forceinline__ void load_stage(uint32_t tile0, int m0, int n0, int k_it, int slot,
                                           int tid) {
    const int k0 = k_it * BK;
    const uint32_t sa = tile0 + slot * STAGE_BYTES;
    const uint32_t sbm = sa + A_STAGE_BYTES;
#pragma unroll
    for (int c = tid; c < 3072; c += 512) {
        if (c < 2048) {
            const int r = c >> 3, j = c & 7;
            cp_async16(sa + swz((uint32_t)(r * 128 + j * 16)),
                       g_A + (((size_t)(m0 + r)) << 12) + k0 + (j << 3));
        } else {
            const int c2 = c - 2048;
            const int r = c2 >> 3, j = c2 & 7;
            cp_async16(sbm + swz((uint32_t)(r * 128 + j * 16)),
                       g_B + (((size_t)(n0 + r)) << 12) + k0 + (j << 3));
        }
    }
}

__global__ void __launch_bounds__(512, 1) gemm_kernel(float* __restrict__ out,
                                                      const float* __restrict__ bias) {
    extern __shared__ char smem[];
    const uint32_t tile0 = (smem_u32(smem) + 1023) & ~1023u;
    const int tid = threadIdx.x;
    const int wid = tid >> 5;
    const int lane = tid & 31;
    const int m0 = blockIdx.y * BM;
    const int n0 = blockIdx.x * BN;
    const int warp_m = wid & 3;        // 0..3 -> 64 rows each
    const int warp_n = wid >> 2;       // 0..3 -> 32 cols each

    // Swizzled ldmatrix offsets (kk=0).
    uint32_t aoff[4];
#pragma unroll
    for (int mi = 0; mi < 4; ++mi) {
        const int row = warp_m * 64 + mi * 16 + (lane & 15);
        aoff[mi] = swz((uint32_t)(row * 128) + (uint32_t)((lane >> 4) << 4));
    }
    uint32_t boff[2];
#pragma unroll
    for (int pj = 0; pj < 2; ++pj) {
        const int row = warp_n * 32 + pj * 16 + (lane & 7) + ((lane >> 4) << 3);
        boff[pj] = swz((uint32_t)(row * 128) + (uint32_t)(((lane >> 3) & 1) << 4));
    }

    float acc[4][4][4];   // [mi][nj][c]
#pragma unroll
    for (int mi = 0; mi < 4; ++mi)
#pragma unroll
        for (int nj = 0; nj < 4; ++nj)
#pragma unroll
            for (int c = 0; c < 4; ++c) acc[mi][nj][c] = 0.0f;

    // Prologue: fill stages 0..2 (3 commit groups)
#pragma unroll
    for (int p = 0; p < STAGES - 1; ++p) {
        load_stage(tile0, m0, n0, p, p, tid);
        cp_commit();
    }
    cp_wait<1>();       // stages 0,1 resident
    __syncthreads();

    // Preload kk=0 fragments of stage 0 (live across iteration boundaries).
    uint32_t bcur[4][2], bnxt[4][2];
    uint32_t acur[4], anxt[4];
    {
        uint32_t r0, r1, r2, r3;
        ldsm_x4(r0, r1, r2, r3, tile0 + A_STAGE_BYTES + boff[0]);
        bcur[0][0] = r0; bcur[0][1] = r1; bcur[1][0] = r2; bcur[1][1] = r3;
        ldsm_x4(r0, r1, r2, r3, tile0 + A_STAGE_BYTES + boff[1]);
        bcur[2][0] = r0; bcur[2][1] = r1; bcur[3][0] = r2; bcur[3][1] = r3;
        ldsm_x4(acur[0], acur[1], acur[2], acur[3], tile0 + aoff[0]);
    }

    for (int it = 0; it < NIT; ++it) {
        const uint32_t sa = tile0 + (it % STAGES) * STAGE_BYTES;
        const uint32_t sbm = sa + A_STAGE_BYTES;
        const uint32_t sa_n = tile0 + ((it + 1) % STAGES) * STAGE_BYTES;
        const uint32_t sbm_n = sa_n + A_STAGE_BYTES;
        const bool has_next = (it + 1 < NIT);

        // Issue loads for stage it+3 (slot freed by the barrier at end of iter it-1).
        if (it + STAGES - 1 < NIT)
            load_stage(tile0, m0, n0, it + STAGES - 1, (it + STAGES - 1) % STAGES, tid);
        cp_commit();

#pragma unroll
        for (int kk = 0; kk < 4; ++kk) {
            const uint32_t kx = (uint32_t)(kk << 5);
            const uint32_t kxn = (uint32_t)((kk + 1) << 5);
            // Prefetch next kk's B (kk<3) or next ITER's kk0 B (kk==3, stage it+1 resident).
            if (kk < 3) {
                uint32_t r0, r1, r2, r3;
                ldsm_x4(r0, r1, r2, r3, sbm + (boff[0] ^ kxn));
                bnxt[0][0] = r0; bnxt[0][1] = r1; bnxt[1][0] = r2; bnxt[1][1] = r3;
                ldsm_x4(r0, r1, r2, r3, sbm + (boff[1] ^ kxn));
                bnxt[2][0] = r0; bnxt[2][1] = r1; bnxt[3][0] = r2; bnxt[3][1] = r3;
            } else if (has_next) {
                uint32_t r0, r1, r2, r3;
                ldsm_x4(r0, r1, r2, r3, sbm_n + boff[0]);
                bnxt[0][0] = r0; bnxt[0][1] = r1; bnxt[1][0] = r2; bnxt[1][1] = r3;
                ldsm_x4(r0, r1, r2, r3, sbm_n + boff[1]);
                bnxt[2][0] = r0; bnxt[2][1] = r1; bnxt[3][0] = r2; bnxt[3][1] = r3;
            }
#pragma unroll
            for (int mi = 0; mi < 4; ++mi) {
                if (mi < 3)
                    ldsm_x4(anxt[0], anxt[1], anxt[2], anxt[3], sa + (aoff[mi + 1] ^ kx));
                else if (kk < 3)
                    ldsm_x4(anxt[0], anxt[1], anxt[2], anxt[3], sa + (aoff[0] ^ kxn));
                else if (has_next)
                    ldsm_x4(anxt[0], anxt[1], anxt[2], anxt[3], sa_n + aoff[0]);
#pragma unroll
                for (int nj = 0; nj < 4; ++nj)
                    mma16816(acc[mi][nj][0], acc[mi][nj][1], acc[mi][nj][2], acc[mi][nj][3],
                             acur[0], acur[1], acur[2], acur[3],
                             bcur[nj][0], bcur[nj][1]);
#pragma unroll
                for (int q = 0; q < 4; ++q) acur[q] = anxt[q];
            }
#pragma unroll
            for (int nj = 0; nj < 4; ++nj) {
                bcur[nj][0] = bnxt[nj][0];
                bcur[nj][1] = bnxt[nj][1];
            }
        }

        // End-of-iter: stage it+2 guaranteed resident for next iter's kk3 prefetch;
        // barrier frees slot (it+4)%4 (= stage it's slot) for next iter's writers.
        cp_wait<1>();
        __syncthreads();
    }

    // Epilogue
    const int g = lane >> 2, tg = lane & 3;
#pragma unroll
    for (int mi = 0; mi < 4; ++mi) {
        const int r0 = m0 + warp_m * 64 + mi * 16 + g;
        float* o0 = out + (size_t)r0 * N;
        float* o1 = out + (size_t)(r0 + 8) * N;
#pragma unroll
        for (int nj = 0; nj < 4; ++nj) {
            const int col = n0 + warp_n * 32 + nj * 8 + tg * 2;
            const float b0 = __ldg(bias + col);
            const float b1 = __ldg(bias + col + 1);
            float2 v0 = make_float2(acc[mi][nj][0] + b0, acc[mi][nj][1] + b1);
            float2 v1 = make_float2(acc[mi][nj][2] + b0, acc[mi][nj][3] + b1);
            *reinterpret_cast<float2*>(o0 + col) = v0;
            *reinterpret_cast<float2*>(o1 + col) = v1;
        }
    }
}

// ---------------- launch ----------------
extern "C" void kernel_launch(void* const* d_in, const int* in_sizes, int n_in,
                              void* d_out, int out_size) {
    const float* x    = (const float*)d_in[0];
    const float* W    = (const float*)d_in[1];
    const float* bias = (const float*)d_in[2];
    float* out = (float*)d_out;

    prep_kernel<<<BIN_BLOCKS + WCONV_BLOCKS, 256>>>((const float4*)x, W);

    cudaFuncSetAttribute(gemm_kernel, cudaFuncAttributeMaxDynamicSharedMemorySize, DYN_SMEM);
    gemm_kernel<<<dim3(N / BN, M / BM), 512, DYN_SMEM>>>(out, bias);
}

// round 12
// speedup vs baseline: 1.3829x; 1.1084x over previous
#include <cuda_runtime.h>
#include <cuda_fp16.h>
#include <cstdint>
#include <cstddef>

// Problem sizes
static constexpr int M = 8192;   // tokens
static constexpr int K = 4096;   // in features
static constexpr int N = 4096;   // out features

// GEMM tiling: CTA 128x256x64, 8 warps (2 M x 4 N), warp tile 64x64, 256 threads.
// Crossbar traffic/iter: 128KB ldsm + 48KB cp.async < HMMA floor -> tensor-bound.
static constexpr int BM = 128;
static constexpr int BN = 256;
static constexpr int BK = 64;                    // 64 fp16 = 128 B per row
static constexpr int NIT = K / BK;               // 64
static constexpr int STAGES = 4;
static constexpr int A_STAGE_BYTES = BM * 128;   // 16 KB
static constexpr int B_STAGE_BYTES = BN * 128;   // 32 KB
static constexpr int STAGE_BYTES = A_STAGE_BYTES + B_STAGE_BYTES;  // 48 KB
static constexpr int DYN_SMEM = 1024 + STAGES * STAGE_BYTES;       // ~193 KB

// Scratch (static device arrays are allowed; cudaMalloc is not)
__device__ __half g_A[(size_t)M * K];   // sign(x) as fp16, [M,K] row-major
__device__ __half g_B[(size_t)N * K];   // W^T as fp16,     [N,K] row-major

// ---------------- PTX helpers (baseline sm_103, no 'a' features) ----------------
__device__ __forceinline__ uint32_t smem_u32(const void* p) {
    uint32_t a;
    asm("{ .reg .u64 t; cvta.to.shared.u64 t, %1; cvt.u32.u64 %0, t; }" : "=r"(a) : "l"(p));
    return a;
}
__device__ __forceinline__ void cp_async16(uint32_t s, const void* g) {
    asm volatile("cp.async.cg.shared.global [%0], [%1], 16;" :: "r"(s), "l"(g));
}
__device__ __forceinline__ void cp_commit() {
    asm volatile("cp.async.commit_group;" ::: "memory");
}
template <int NWAIT>
__device__ __forceinline__ void cp_wait() {
    asm volatile("cp.async.wait_group %0;" :: "n"(NWAIT) : "memory");
}
__device__ __forceinline__ void ldsm_x4(uint32_t& r0, uint32_t& r1, uint32_t& r2, uint32_t& r3,
                                        uint32_t addr) {
    asm volatile("ldmatrix.sync.aligned.m8n8.x4.shared.b16 {%0,%1,%2,%3}, [%4];"
                 : "=r"(r0), "=r"(r1), "=r"(r2), "=r"(r3) : "r"(addr));
}
__device__ __forceinline__ void mma16816(float& d0, float& d1, float& d2, float& d3,
                                         uint32_t a0, uint32_t a1, uint32_t a2, uint32_t a3,
                                         uint32_t b0, uint32_t b1) {
    asm volatile(
        "mma.sync.aligned.m16n8k16.row.col.f32.f16.f16.f32 "
        "{%0,%1,%2,%3}, {%4,%5,%6,%7}, {%8,%9}, {%0,%1,%2,%3};"
        : "+f"(d0), "+f"(d1), "+f"(d2), "+f"(d3)
        : "r"(a0), "r"(a1), "r"(a2), "r"(a3), "r"(b0), "r"(b1));
}
// SW128-style swizzle: XOR 16B-chunk index with (row & 7)
__device__ __forceinline__ uint32_t swz(uint32_t off) { return off ^ ((off >> 3) & 0x70); }

// ---------------- Kernel 1: fused prep ----------------
static constexpr int BIN_BLOCKS = 4096;
static constexpr int WCONV_BLOCKS = (N / 32) * (K / 64);   // 8192
__global__ void prep_kernel(const float4* __restrict__ x4, const float* __restrict__ W) {
    if (blockIdx.x < BIN_BLOCKS) {
        const int n4 = (M * K) / 4;
        int i = blockIdx.x * 256 + threadIdx.x;
        const int stride = BIN_BLOCKS * 256;
        const __half one = __float2half_rn(1.0f);
        const __half neg = __float2half_rn(-1.0f);
        uint2* a8 = reinterpret_cast<uint2*>(g_A);
        for (; i < n4; i += stride) {
            float4 v = x4[i];
            __half2 h0 = __halves2half2(v.x > 0.0f ? one : neg, v.y > 0.0f ? one : neg);
            __half2 h1 = __halves2half2(v.z > 0.0f ? one : neg, v.w > 0.0f ? one : neg);
            uint2 pk;
            pk.x = *reinterpret_cast<uint32_t*>(&h0);
            pk.y = *reinterpret_cast<uint32_t*>(&h1);
            a8[i] = pk;
        }
    } else {
        __shared__ float t[64][33];
        const int bid = blockIdx.x - BIN_BLOCKS;
        const int n0 = (bid & 127) * 32;       // N/32 = 128
        const int k0 = (bid >> 7) * 64;
        const int tx = threadIdx.x & 31, ty = threadIdx.x >> 5;   // 32 x 8
#pragma unroll
        for (int r = 0; r < 8; ++r)
            t[ty + 8 * r][tx] = W[(size_t)(k0 + ty + 8 * r) * N + n0 + tx];
        __syncthreads();
#pragma unroll
        for (int r = 0; r < 4; ++r) {
            const int n = ty + 8 * r;          // 0..31
            const __half2 h = __floats2half2_rn(t[2 * tx][n], t[2 * tx + 1][n]);
            *reinterpret_cast<__half2*>(g_B + (size_t)(n0 + n) * K + k0 + 2 * tx) = h;
        }
    }
}

// ---------------- Kernel 2: mma.sync fp16 GEMM + bias ----------------
__device__ __forceinline__ void load_stage(uint32_t tile0, int m0, int n0, int k_it, int slot,
                                           int tid) {
    const int k0 = k_it * BK;
    const uint32_t sa = tile0 + slot * STAGE_BYTES;
    const uint32_t sbm = sa + A_STAGE_BYTES;
    // A: 128 rows x 8 chunks = 1024; B: 256 rows x 8 chunks = 2048; 3072 / 256 thr = 12 each
#pragma unroll
    for (int c = tid; c < 3072; c += 256) {
        if (c < 1024) {
            const int r = c >> 3, j = c & 7;
            cp_async16(sa + swz((uint32_t)(r * 128 + j * 16)),
                       g_A + (((size_t)(m0 + r)) << 12) + k0 + (j << 3));
        } else {
            const int c2 = c - 1024;
            const int r = c2 >> 3, j = c2 & 7;
            cp_async16(sbm + swz((uint32_t)(r * 128 + j * 16)),
                       g_B + (((size_t)(n0 + r)) << 12) + k0 + (j << 3));
        }
    }
}

// Load one kk-step's fragments for this warp: A 4x ldsm.x4, B 4x ldsm.x4.
__device__ __forceinline__ void load_frags(uint32_t af[4][4], uint32_t bf[8][2],
                                           uint32_t sa, uint32_t sbm,
                                           const uint32_t aoff[4], const uint32_t boff[4],
                                           uint32_t kx) {
#pragma unroll
    for (int mi = 0; mi < 4; ++mi)
        ldsm_x4(af[mi][0], af[mi][1], af[mi][2], af[mi][3], sa + (aoff[mi] ^ kx));
#pragma unroll
    for (int pj = 0; pj < 4; ++pj) {
        uint32_t r0, r1, r2, r3;
        ldsm_x4(r0, r1, r2, r3, sbm + (boff[pj] ^ kx));
        bf[pj * 2 + 0][0] = r0; bf[pj * 2 + 0][1] = r1;
        bf[pj * 2 + 1][0] = r2; bf[pj * 2 + 1][1] = r3;
    }
}

__global__ void __launch_bounds__(256, 1) gemm_kernel(float* __restrict__ out,
                                                      const float* __restrict__ bias) {
    extern __shared__ char smem[];
    const uint32_t tile0 = (smem_u32(smem) + 1023) & ~1023u;
    const int tid = threadIdx.x;
    const int wid = tid >> 5;
    const int lane = tid & 31;
    const int m0 = blockIdx.y * BM;
    const int n0 = blockIdx.x * BN;
    const int warp_m = wid & 1;        // 0..1 -> 64 rows each
    const int warp_n = wid >> 1;       // 0..3 -> 64 cols each

    // Swizzled ldmatrix offsets (kk=0).
    uint32_t aoff[4];
#pragma unroll
    for (int mi = 0; mi < 4; ++mi) {
        const int row = warp_m * 64 + mi * 16 + (lane & 15);
        aoff[mi] = swz((uint32_t)(row * 128) + (uint32_t)((lane >> 4) << 4));
    }
    uint32_t boff[4];
#pragma unroll
    for (int pj = 0; pj < 4; ++pj) {
        const int row = warp_n * 64 + pj * 16 + (lane & 7) + ((lane >> 4) << 3);
        boff[pj] = swz((uint32_t)(row * 128) + (uint32_t)(((lane >> 3) & 1) << 4));
    }

    float acc[4][8][4];   // [mi][nj][c]  (128 regs)
#pragma unroll
    for (int mi = 0; mi < 4; ++mi)
#pragma unroll
        for (int nj = 0; nj < 8; ++nj)
#pragma unroll
            for (int c = 0; c < 4; ++c) acc[mi][nj][c] = 0.0f;

    // Prologue: fill stages 0..2
#pragma unroll
    for (int p = 0; p < STAGES - 1; ++p) {
        load_stage(tile0, m0, n0, p, p, tid);
        cp_commit();
    }
    cp_wait<1>();       // stages 0,1 resident
    __syncthreads();

    // Full kk-step double buffer: A 2x16 regs, B 2x16 regs.
    uint32_t af[2][4][4];
    uint32_t bf[2][8][2];
    load_frags(af[0], bf[0], tile0, tile0 + A_STAGE_BYTES, aoff, boff, 0);

    for (int it = 0; it < NIT; ++it) {
        const uint32_t sa = tile0 + (it % STAGES) * STAGE_BYTES;
        const uint32_t sbm = sa + A_STAGE_BYTES;
        const uint32_t sa_n = tile0 + ((it + 1) % STAGES) * STAGE_BYTES;
        const uint32_t sbm_n = sa_n + A_STAGE_BYTES;
        const bool has_next = (it + 1 < NIT);

        // Issue loads for stage it+3 (slot freed by barrier at end of iter it-1).
        if (it + STAGES - 1 < NIT)
            load_stage(tile0, m0, n0, it + STAGES - 1, (it + STAGES - 1) % STAGES, tid);
        cp_commit();

#pragma unroll
        for (int kk = 0; kk < 4; ++kk) {
            const int cur = kk & 1, nxt = cur ^ 1;
            // Prefetch kk+1 (same stage) or next iter's kk0 (stage it+1, resident).
            if (kk < 3)
                load_frags(af[nxt], bf[nxt], sa, sbm, aoff, boff, (uint32_t)((kk + 1) << 5));
            else if (has_next)
                load_frags(af[nxt], bf[nxt], sa_n, sbm_n, aoff, boff, 0);
            // 32 MMAs of latency cover for the prefetch above.
#pragma unroll
            for (int mi = 0; mi < 4; ++mi)
#pragma unroll
                for (int nj = 0; nj < 8; ++nj)
                    mma16816(acc[mi][nj][0], acc[mi][nj][1], acc[mi][nj][2], acc[mi][nj][3],
                             af[cur][mi][0], af[cur][mi][1], af[cur][mi][2], af[cur][mi][3],
                             bf[cur][nj][0], bf[cur][nj][1]);
        }

        // End-of-iter: guarantee stage it+2 resident (next iter's kk3 prefetch);
        // barrier frees stage it's slot for next iter's writers.
        cp_wait<1>();
        __syncthreads();
    }

    // Epilogue
    const int g = lane >> 2, tg = lane & 3;
#pragma unroll
    for (int mi = 0; mi < 4; ++mi) {
        const int r0 = m0 + warp_m * 64 + mi * 16 + g;
        float* o0 = out + (size_t)r0 * N;
        float* o1 = out + (size_t)(r0 + 8) * N;
#pragma unroll
        for (int nj = 0; nj < 8; ++nj) {
            const int col = n0 + warp_n * 64 + nj * 8 + tg * 2;
            const float b0 = __ldg(bias + col);
            const float b1 = __ldg(bias + col + 1);
            float2 v0 = make_float2(acc[mi][nj][0] + b0, acc[mi][nj][1] + b1);
            float2 v1 = make_float2(acc[mi][nj][2] + b0, acc[mi][nj][3] + b1);
            *reinterpret_cast<float2*>(o0 + col) = v0;
            *reinterpret_cast<float2*>(o1 + col) = v1;
        }
    }
}

// ---------------- launch ----------------
extern "C" void kernel_launch(void* const* d_in, const int* in_sizes, int n_in,
                              void* d_out, int out_size) {
    const float* x    = (const float*)d_in[0];
    const float* W    = (const float*)d_in[1];
    const float* bias = (const float*)d_in[2];
    float* out = (float*)d_out;

    prep_kernel<<<BIN_BLOCKS + WCONV_BLOCKS, 256>>>((const float4*)x, W);

    cudaFuncSetAttribute(gemm_kernel, cudaFuncAttributeMaxDynamicSharedMemorySize, DYN_SMEM);
    gemm_kernel<<<dim3(N / BN, M / BM), 256, DYN_SMEM>>>(out, bias);
}